// round 10
// baseline (speedup 1.0000x reference)
#include <cuda_runtime.h>
#include <cuda_bf16.h>
#include <math.h>
#include <stdint.h>

// ---------------- problem constants ----------------
#define NLAYERS 4
#define NHEADS  8
#define DMODEL  256
#define DFF     1024
#define BATCH   2
#define SEQ     2048
#define MTOT    (BATCH * SEQ)   // 4096 rows
#define HD      32              // head dim
#define QKVS    768             // fused QKV row stride

// ---------------- scratch (device globals; no allocation allowed) ----------
__device__ float g_h   [MTOT * DMODEL];          // residual stream (fp32)
__device__ float g_unc [BATCH * NHEADS * SEQ];
__device__ float g_bqkv[NLAYERS * QKVS];

// split bf16 activation planes
__device__ __nv_bfloat16 g_xH   [MTOT * DMODEL];
__device__ __nv_bfloat16 g_xL   [MTOT * DMODEL];
__device__ __nv_bfloat16 g_lnH  [MTOT * DMODEL];
__device__ __nv_bfloat16 g_lnL  [MTOT * DMODEL];
__device__ __nv_bfloat16 g_qkvH [MTOT * QKVS];
__device__ __nv_bfloat16 g_qkvL [MTOT * QKVS];
__device__ __nv_bfloat16 g_attnH[MTOT * DMODEL];
__device__ __nv_bfloat16 g_attnL[MTOT * DMODEL];
__device__ __nv_bfloat16 g_ffH  [MTOT * DFF];
__device__ __nv_bfloat16 g_ffL  [MTOT * DFF];

// bf16 split weights (hi/lo planes), transposed to [N][K]
__device__ __nv_bfloat16 g_WinH [DMODEL * DMODEL];
__device__ __nv_bfloat16 g_WinL [DMODEL * DMODEL];
__device__ __nv_bfloat16 g_WoutH[DMODEL * DMODEL];
__device__ __nv_bfloat16 g_WoutL[DMODEL * DMODEL];
__device__ __nv_bfloat16 g_WqkvH[NLAYERS * QKVS * DMODEL];
__device__ __nv_bfloat16 g_WqkvL[NLAYERS * QKVS * DMODEL];
__device__ __nv_bfloat16 g_WoH  [NLAYERS * DMODEL * DMODEL];
__device__ __nv_bfloat16 g_WoL  [NLAYERS * DMODEL * DMODEL];
__device__ __nv_bfloat16 g_W1H  [NLAYERS * DFF * DMODEL];
__device__ __nv_bfloat16 g_W1L  [NLAYERS * DFF * DMODEL];
__device__ __nv_bfloat16 g_W2H  [NLAYERS * DMODEL * DFF];
__device__ __nv_bfloat16 g_W2L  [NLAYERS * DMODEL * DFF];

// ---------------- prep kernels ----------------------------------------------
struct PrepSeg {
    const float* src;
    __nv_bfloat16* hi;
    __nv_bfloat16* lo;
    int K;
    int N;
    int base;      // cumulative element offset
};
struct PrepArgs { PrepSeg s[26]; int total; };

__global__ void prep_kernel(PrepArgs a)
{
    int gidx = blockIdx.x * 256 + threadIdx.x;
    if (gidx >= a.total) return;
    // find segment (uniform across most blocks)
    int si = 0;
    #pragma unroll
    for (int i = 1; i < 26; i++)
        if (gidx >= a.s[i].base) si = i;
    PrepSeg sg = a.s[si];
    int idx = gidx - sg.base;
    int k = idx % sg.K, n = idx / sg.K;
    float v = sg.src[(size_t)k * sg.N + n];
    __nv_bfloat16 h = __float2bfloat16(v);
    sg.hi[idx] = h;
    sg.lo[idx] = __float2bfloat16(v - __bfloat162float(h));
}

__global__ void splitx_kernel(const float* __restrict__ x)
{
    int idx = blockIdx.x * 256 + threadIdx.x;
    if (idx < MTOT * DMODEL) {
        float v = x[idx];
        __nv_bfloat16 h = __float2bfloat16(v);
        g_xH[idx] = h;
        g_xL[idx] = __float2bfloat16(v - __bfloat162float(h));
    }
}

__global__ void misc_kernel(const float* __restrict__ bq,
                            const float* __restrict__ bk,
                            const float* __restrict__ bv)
{
    int idx = blockIdx.x * 256 + threadIdx.x;
    if (idx < NLAYERS * QKVS) {
        int l = idx / QKVS, c = idx % QKVS;
        int sec = c >> 8, cc = c & 255;
        const float* s = (sec == 0) ? bq : (sec == 1 ? bk : bv);
        g_bqkv[idx] = s[l * DMODEL + cc];
    }
    int j = idx - NLAYERS * QKVS;
    if (j >= 0 && j < BATCH * NHEADS * SEQ) g_unc[j] = 0.f;
}

// ---------------- layernorm: warp-per-row, no block barriers ---------------
__global__ void __launch_bounds__(256)
ln_kernel(const float* __restrict__ x,
          const float* __restrict__ gamma,
          const float* __restrict__ beta,
          __nv_bfloat16* __restrict__ yH,
          __nv_bfloat16* __restrict__ yL)
{
    int warp = threadIdx.x >> 5, lane = threadIdx.x & 31;
    int row = blockIdx.x * 8 + warp;
    const float* xr = x + (size_t)row * DMODEL + lane * 8;

    float4 a = *(const float4*)xr;
    float4 b = *(const float4*)(xr + 4);

    float s = a.x + a.y + a.z + a.w + b.x + b.y + b.z + b.w;
    #pragma unroll
    for (int o = 16; o > 0; o >>= 1) s += __shfl_xor_sync(0xffffffffu, s, o);
    float mean = s * (1.0f / DMODEL);

    float v[8] = { a.x - mean, a.y - mean, a.z - mean, a.w - mean,
                   b.x - mean, b.y - mean, b.z - mean, b.w - mean };
    float s2 = 0.f;
    #pragma unroll
    for (int i = 0; i < 8; i++) s2 += v[i] * v[i];
    #pragma unroll
    for (int o = 16; o > 0; o >>= 1) s2 += __shfl_xor_sync(0xffffffffu, s2, o);
    float rstd = rsqrtf(s2 * (1.0f / DMODEL) + 1e-5f);

    float4 g0 = *(const float4*)&gamma[lane * 8];
    float4 g1 = *(const float4*)&gamma[lane * 8 + 4];
    float4 be0 = *(const float4*)&beta[lane * 8];
    float4 be1 = *(const float4*)&beta[lane * 8 + 4];
    float gg[8] = { g0.x, g0.y, g0.z, g0.w, g1.x, g1.y, g1.z, g1.w };
    float bb[8] = { be0.x, be0.y, be0.z, be0.w, be1.x, be1.y, be1.z, be1.w };

    __nv_bfloat16 hh[8], ll[8];
    #pragma unroll
    for (int i = 0; i < 8; i++) {
        float y = v[i] * rstd * gg[i] + bb[i];
        __nv_bfloat16 h = __float2bfloat16(y);
        hh[i] = h;
        ll[i] = __float2bfloat16(y - __bfloat162float(h));
    }
    size_t o = (size_t)row * DMODEL + lane * 8;
    *(uint4*)&yH[o] = *(uint4*)hh;
    *(uint4*)&yL[o] = *(uint4*)ll;
}

// ---------------- mma / cp.async helpers ------------------------------------
__device__ __forceinline__ uint32_t smem_u32(const void* p)
{
    return (uint32_t)__cvta_generic_to_shared(p);
}

__device__ __forceinline__ void ldsm_x4(uint32_t& r0, uint32_t& r1,
                                        uint32_t& r2, uint32_t& r3, uint32_t addr)
{
    asm volatile("ldmatrix.sync.aligned.m8n8.x4.shared.b16 {%0,%1,%2,%3}, [%4];\n"
                 : "=r"(r0), "=r"(r1), "=r"(r2), "=r"(r3) : "r"(addr));
}

__device__ __forceinline__ void mma_bf16(float* d, const uint32_t* a, const uint32_t* b)
{
    asm volatile(
        "mma.sync.aligned.m16n8k16.row.col.f32.bf16.bf16.f32 "
        "{%0,%1,%2,%3}, {%4,%5,%6,%7}, {%8,%9}, {%0,%1,%2,%3};\n"
        : "+f"(d[0]), "+f"(d[1]), "+f"(d[2]), "+f"(d[3])
        : "r"(a[0]), "r"(a[1]), "r"(a[2]), "r"(a[3]), "r"(b[0]), "r"(b[1]));
}

__device__ __forceinline__ void split_bf16x2(float a, float b,
                                             __nv_bfloat162& hi, __nv_bfloat162& lo)
{
    __nv_bfloat16 h0 = __float2bfloat16(a);
    __nv_bfloat16 h1 = __float2bfloat16(b);
    hi.x = h0; hi.y = h1;
    lo.x = __float2bfloat16(a - __bfloat162float(h0));
    lo.y = __float2bfloat16(b - __bfloat162float(h1));
}

__device__ __forceinline__ void cp16(void* dst, const void* src)
{
    asm volatile("cp.async.cg.shared.global [%0], [%1], 16;\n"
                 :: "r"(smem_u32(dst)), "l"(src));
}
__device__ __forceinline__ void cp_commit()
{
    asm volatile("cp.async.commit_group;\n");
}
template <int N>
__device__ __forceinline__ void cp_wait()
{
    asm volatile("cp.async.wait_group %0;\n" :: "n"(N));
}

// ---------------- pipelined pre-split bf16 GEMM -----------------------------
// Tile 64x64, BK=32, 256 threads (8 warps, 2x4 grid, 32x16 per warp),
// 2-stage cp.async, one __syncthreads per k-iter.
#define GASZ (64 * 40)
#define GBSZ (64 * 40)
#define GSTG (2 * GASZ + 2 * GBSZ)           // elems per stage (10240)
#define GEMM_SMEM (2 * GSTG * 2)             // bytes = 40960

// Shared mainloop: accumulates A[kbase:kbase+kspan] @ B into acc.
template <typename T>
__device__ __forceinline__ void gemm_mainloop(
    const __nv_bfloat16* Ah_, const __nv_bfloat16* Al_,
    const __nv_bfloat16* Bh_, const __nv_bfloat16* Bl_,
    __nv_bfloat16* sm, int m0, int n0, int K, int kbase, int kspan,
    int wm, int wn, int frow, int fcolh, T& acc)
{
    int tid = threadIdx.x;
    int lrw = tid >> 2, lc8 = (tid & 3) * 8;

    auto load_stage = [&](int stage, int k0) {
        __nv_bfloat16* base = sm + stage * GSTG;
        cp16(&base[lrw * 40 + lc8],                   &Ah_[(size_t)(m0 + lrw) * K + k0 + lc8]);
        cp16(&base[GASZ + lrw * 40 + lc8],            &Al_[(size_t)(m0 + lrw) * K + k0 + lc8]);
        cp16(&base[2 * GASZ + lrw * 40 + lc8],        &Bh_[(size_t)(n0 + lrw) * K + k0 + lc8]);
        cp16(&base[2 * GASZ + GBSZ + lrw * 40 + lc8], &Bl_[(size_t)(n0 + lrw) * K + k0 + lc8]);
        cp_commit();
    };

    load_stage(0, kbase);

    int kiters = kspan >> 5;
    for (int it = 0; it < kiters; it++) {
        int stage = it & 1;
        cp_wait<0>();
        __syncthreads();
        if (it + 1 < kiters) load_stage(stage ^ 1, kbase + (it + 1) * 32);

        __nv_bfloat16* sAh = sm + stage * GSTG;
        __nv_bfloat16* sAl = sAh + GASZ;
        __nv_bfloat16* sBh = sAh + 2 * GASZ;
        __nv_bfloat16* sBl = sBh + GBSZ;

        #pragma unroll
        for (int s = 0; s < 2; s++) {
            int kb = s * 16;
            uint32_t ah[2][4], al[2][4], bh[2][2], bl[2][2];
            #pragma unroll
            for (int mt = 0; mt < 2; mt++) {
                uint32_t addr = smem_u32(&sAh[(wm * 32 + mt * 16 + frow) * 40 + kb + fcolh]);
                ldsm_x4(ah[mt][0], ah[mt][1], ah[mt][2], ah[mt][3], addr);
                addr = smem_u32(&sAl[(wm * 32 + mt * 16 + frow) * 40 + kb + fcolh]);
                ldsm_x4(al[mt][0], al[mt][1], al[mt][2], al[mt][3], addr);
            }
            {
                uint32_t r0, r1, r2, r3;
                uint32_t addr = smem_u32(&sBh[(wn * 16 + frow) * 40 + kb + fcolh]);
                ldsm_x4(r0, r1, r2, r3, addr);
                bh[0][0] = r0; bh[1][0] = r1; bh[0][1] = r2; bh[1][1] = r3;
                addr = smem_u32(&sBl[(wn * 16 + frow) * 40 + kb + fcolh]);
                ldsm_x4(r0, r1, r2, r3, addr);
                bl[0][0] = r0; bl[1][0] = r1; bl[0][1] = r2; bl[1][1] = r3;
            }
            #pragma unroll
            for (int mt = 0; mt < 2; mt++)
                #pragma unroll
                for (int nt = 0; nt < 2; nt++) {
                    mma_bf16(acc[mt][nt], ah[mt], bh[nt]);
                    mma_bf16(acc[mt][nt], ah[mt], bl[nt]);
                    mma_bf16(acc[mt][nt], al[mt], bh[nt]);
                }
        }
    }
}

template <int EPI, int SPLIT>
__global__ void __launch_bounds__(256)
gemm2(const __nv_bfloat16* __restrict__ Ah_, const __nv_bfloat16* __restrict__ Al_,
      const __nv_bfloat16* __restrict__ Bh_, const __nv_bfloat16* __restrict__ Bl_,
      const float* __restrict__ bias, const float* __restrict__ res,
      float* __restrict__ C, __nv_bfloat16* __restrict__ Ch, __nv_bfloat16* __restrict__ Cl,
      int K, int ldc)
{
    extern __shared__ __align__(16) __nv_bfloat16 sm[];
    int tid = threadIdx.x, lane = tid & 31, warp = tid >> 5;
    int m0 = blockIdx.y * 64, n0 = blockIdx.x * 64;
    int wm = warp >> 2, wn = warp & 3;
    int gq = lane >> 3, lr = lane & 7;
    int frow = (gq & 1) * 8 + lr, fcolh = (gq >> 1) * 8;

    float acc[2][2][4] = {};
    gemm_mainloop(Ah_, Al_, Bh_, Bl_, sm, m0, n0, K, 0, K, wm, wn, frow, fcolh, acc);

    int gid = lane >> 2, tg = lane & 3;
    #pragma unroll
    for (int mt = 0; mt < 2; mt++) {
        int row0 = m0 + wm * 32 + mt * 16 + gid;
        #pragma unroll
        for (int nt = 0; nt < 2; nt++) {
            int col = n0 + wn * 16 + nt * 8 + tg * 2;
            #pragma unroll
            for (int half = 0; half < 2; half++) {
                int row = row0 + half * 8;
                float v0 = acc[mt][nt][half * 2 + 0] + bias[col];
                float v1 = acc[mt][nt][half * 2 + 1] + bias[col + 1];
                if (EPI == 1) {
                    v0 += res[(size_t)row * ldc + col];
                    v1 += res[(size_t)row * ldc + col + 1];
                }
                if (EPI == 2) {
                    v0 = 0.5f * v0 * (1.0f + erff(v0 * 0.70710678118654752f));
                    v1 = 0.5f * v1 * (1.0f + erff(v1 * 0.70710678118654752f));
                }
                if (SPLIT) {
                    __nv_bfloat162 hh, ll;
                    split_bf16x2(v0, v1, hh, ll);
                    *(__nv_bfloat162*)&Ch[(size_t)row * ldc + col] = hh;
                    *(__nv_bfloat162*)&Cl[(size_t)row * ldc + col] = ll;
                } else {
                    float2 f2; f2.x = v0; f2.y = v1;
                    *(float2*)&C[(size_t)row * ldc + col] = f2;
                }
            }
        }
    }
}

// Split-K variant: C (fp32, already holding residual) += partial via atomicAdd;
// z==0 chunk also adds bias. grid.z = K / KCHUNK.
#define KCHUNK 256
__global__ void __launch_bounds__(256)
gemm2_sk(const __nv_bfloat16* __restrict__ Ah_, const __nv_bfloat16* __restrict__ Al_,
         const __nv_bfloat16* __restrict__ Bh_, const __nv_bfloat16* __restrict__ Bl_,
         const float* __restrict__ bias, float* __restrict__ C,
         int K, int ldc)
{
    extern __shared__ __align__(16) __nv_bfloat16 sm[];
    int tid = threadIdx.x, lane = tid & 31, warp = tid >> 5;
    int m0 = blockIdx.y * 64, n0 = blockIdx.x * 64;
    int z = blockIdx.z;
    int wm = warp >> 2, wn = warp & 3;
    int gq = lane >> 3, lr = lane & 7;
    int frow = (gq & 1) * 8 + lr, fcolh = (gq >> 1) * 8;

    float acc[2][2][4] = {};
    gemm_mainloop(Ah_, Al_, Bh_, Bl_, sm, m0, n0, K, z * KCHUNK, KCHUNK,
                  wm, wn, frow, fcolh, acc);

    int gid = lane >> 2, tg = lane & 3;
    #pragma unroll
    for (int mt = 0; mt < 2; mt++) {
        int row0 = m0 + wm * 32 + mt * 16 + gid;
        #pragma unroll
        for (int nt = 0; nt < 2; nt++) {
            int col = n0 + wn * 16 + nt * 8 + tg * 2;
            #pragma unroll
            for (int half = 0; half < 2; half++) {
                int row = row0 + half * 8;
                float v0 = acc[mt][nt][half * 2 + 0];
                float v1 = acc[mt][nt][half * 2 + 1];
                if (z == 0) { v0 += bias[col]; v1 += bias[col + 1]; }
                atomicAdd(&C[(size_t)row * ldc + col], v0);
                atomicAdd(&C[(size_t)row * ldc + col + 1], v1);
            }
        }
    }
}

// ---------------- tensor-core fused evidential attention (64-q tiles) ------
// Block: 64 queries x one (b,h), 256 threads (8 warps, 4x2 grid).
// smem ~48 KB -> 3-4 blocks/SM resident at grid 512.
#define ATTN_SMEM 48384

__global__ void __launch_bounds__(256)
attn_mma(const __nv_bfloat16* __restrict__ qkvH,
         const __nv_bfloat16* __restrict__ qkvL,
         __nv_bfloat16* __restrict__ outH,
         __nv_bfloat16* __restrict__ outL,
         float* __restrict__ unc,
         const float* __restrict__ ev_scale,
         const float* __restrict__ ev_bias,
         int layer)
{
    extern __shared__ __align__(16) char smraw[];
    __nv_bfloat16* sQh = (__nv_bfloat16*)smraw;          // [64][40]
    __nv_bfloat16* sQl = sQh + 64 * 40;
    __nv_bfloat16* sKh = sQl + 64 * 40;                  // [64][40]
    __nv_bfloat16* sKl = sKh + 64 * 40;
    __nv_bfloat16* sVh = sKl + 64 * 40;                  // [32][72] transposed
    __nv_bfloat16* sVl = sVh + 32 * 72;
    __nv_bfloat16* sEh = sVl + 32 * 72;                  // [64][72]
    __nv_bfloat16* sEl = sEh + 64 * 72;
    float* rowsum = (float*)(sEl + 64 * 72);             // [64]

    int tid = threadIdx.x, lane = tid & 31, warp = tid >> 5;
    int bh = blockIdx.y;
    int b = bh >> 3, h = bh & 7;
    int q0 = blockIdx.x * 64;

    float scale = ev_scale[layer];
    float opb   = 1.0f + ev_bias[layer];
    const float inv_sqrt_hd = 0.17677669529663687f;

    const __nv_bfloat16* QbH = qkvH + (size_t)b * SEQ * QKVS + h * HD;
    const __nv_bfloat16* QbL = qkvL + (size_t)b * SEQ * QKVS + h * HD;
    const __nv_bfloat16* KbH = QbH + DMODEL;
    const __nv_bfloat16* KbL = QbL + DMODEL;
    const __nv_bfloat16* VbH = QbH + 2 * DMODEL;
    const __nv_bfloat16* VbL = QbL + 2 * DMODEL;

    if (tid < 64) rowsum[tid] = 0.f;

    // load Q tile 64x32 (both planes): 1 chunk / thread
    {
        int m = tid >> 2, c8 = (tid & 3) * 8;
        *(uint4*)&sQh[m * 40 + c8] = *(const uint4*)&QbH[(size_t)(q0 + m) * QKVS + c8];
        *(uint4*)&sQl[m * 40 + c8] = *(const uint4*)&QbL[(size_t)(q0 + m) * QKVS + c8];
    }

    int wm = warp >> 1, wn = warp & 1;     // 4x2: 16 rows x 32 cols (scores)
    int gq = lane >> 3, lr = lane & 7;
    int frow = (gq & 1) * 8 + lr, fcolh = (gq >> 1) * 8;
    int gid = lane >> 2, tg = lane & 3;

    float acc_ev[2][4] = {};
    float rs[2] = {0.f, 0.f};

    for (int kb0 = 0; kb0 < SEQ; kb0 += 64) {
        __syncthreads();
        // K tile 64x32 both planes
        {
            int m = tid >> 2, c8 = (tid & 3) * 8;
            *(uint4*)&sKh[m * 40 + c8] = *(const uint4*)&KbH[(size_t)(kb0 + m) * QKVS + c8];
            *(uint4*)&sKl[m * 40 + c8] = *(const uint4*)&KbL[(size_t)(kb0 + m) * QKVS + c8];
        }
        // V tile 64x32 -> transposed [32][72], both planes
        #pragma unroll
        for (int e = 0; e < 4; e++) {
            int f = tid + e * 256;
            int key = f >> 4, dp = (f & 15) * 2;
            __nv_bfloat162 vh = *(const __nv_bfloat162*)&VbH[(size_t)(kb0 + key) * QKVS + dp];
            __nv_bfloat162 vl = *(const __nv_bfloat162*)&VbL[(size_t)(kb0 + key) * QKVS + dp];
            sVh[dp * 72 + key]       = vh.x;
            sVh[(dp + 1) * 72 + key] = vh.y;
            sVl[dp * 72 + key]       = vl.x;
            sVl[(dp + 1) * 72 + key] = vl.y;
        }
        __syncthreads();

        // ---- scores: S[64][64]; warp covers 16 rows x 32 cols ----
        float acc_s[4][4] = {};
        #pragma unroll
        for (int s = 0; s < 2; s++) {
            int kb = s * 16;
            uint32_t ah[4], al[4], bhf[4][2], blf[4][2];
            {
                uint32_t addr = smem_u32(&sQh[(wm * 16 + frow) * 40 + kb + fcolh]);
                ldsm_x4(ah[0], ah[1], ah[2], ah[3], addr);
                addr = smem_u32(&sQl[(wm * 16 + frow) * 40 + kb + fcolh]);
                ldsm_x4(al[0], al[1], al[2], al[3], addr);
            }
            #pragma unroll
            for (int np = 0; np < 2; np++) {
                uint32_t r0, r1, r2, r3;
                uint32_t addr = smem_u32(&sKh[(wn * 32 + np * 16 + frow) * 40 + kb + fcolh]);
                ldsm_x4(r0, r1, r2, r3, addr);
                bhf[np * 2][0] = r0; bhf[np * 2 + 1][0] = r1;
                bhf[np * 2][1] = r2; bhf[np * 2 + 1][1] = r3;
                addr = smem_u32(&sKl[(wn * 32 + np * 16 + frow) * 40 + kb + fcolh]);
                ldsm_x4(r0, r1, r2, r3, addr);
                blf[np * 2][0] = r0; blf[np * 2 + 1][0] = r1;
                blf[np * 2][1] = r2; blf[np * 2 + 1][1] = r3;
            }
            #pragma unroll
            for (int nt = 0; nt < 4; nt++) {
                mma_bf16(acc_s[nt], ah, bhf[nt]);
                mma_bf16(acc_s[nt], ah, blf[nt]);
                mma_bf16(acc_s[nt], al, bhf[nt]);
            }
        }

        // ---- evidence + rowsum partials + split to smem ----
        #pragma unroll
        for (int half = 0; half < 2; half++) {
            int row = wm * 16 + half * 8 + gid;
            #pragma unroll
            for (int nt = 0; nt < 4; nt++) {
                float e0 = fmaf(scale, __expf(acc_s[nt][half * 2 + 0] * inv_sqrt_hd), opb);
                float e1 = fmaf(scale, __expf(acc_s[nt][half * 2 + 1] * inv_sqrt_hd), opb);
                rs[half] += e0 + e1;
                int col = wn * 32 + nt * 8 + tg * 2;
                __nv_bfloat162 hh, ll;
                split_bf16x2(e0, e1, hh, ll);
                *(__nv_bfloat162*)&sEh[row * 72 + col] = hh;
                *(__nv_bfloat162*)&sEl[row * 72 + col] = ll;
            }
        }
        __syncthreads();

        // ---- EV += E[64][64] @ V[64][32]; warp: 16 rows x 16 dims ----
        #pragma unroll
        for (int kb = 0; kb < 64; kb += 16) {
            uint32_t eh[4], el[4], vh[2][2], vl[2][2];
            uint32_t addr = smem_u32(&sEh[(wm * 16 + frow) * 72 + kb + fcolh]);
            ldsm_x4(eh[0], eh[1], eh[2], eh[3], addr);
            addr = smem_u32(&sEl[(wm * 16 + frow) * 72 + kb + fcolh]);
            ldsm_x4(el[0], el[1], el[2], el[3], addr);
            {
                uint32_t r0, r1, r2, r3;
                addr = smem_u32(&sVh[(wn * 16 + frow) * 72 + kb + fcolh]);
                ldsm_x4(r0, r1, r2, r3, addr);
                vh[0][0] = r0; vh[1][0] = r1; vh[0][1] = r2; vh[1][1] = r3;
                addr = smem_u32(&sVl[(wn * 16 + frow) * 72 + kb + fcolh]);
                ldsm_x4(r0, r1, r2, r3, addr);
                vl[0][0] = r0; vl[1][0] = r1; vl[0][1] = r2; vl[1][1] = r3;
            }
            #pragma unroll
            for (int nt = 0; nt < 2; nt++) {
                mma_bf16(acc_ev[nt], eh, vh[nt]);
                mma_bf16(acc_ev[nt], eh, vl[nt]);
                mma_bf16(acc_ev[nt], el, vh[nt]);
            }
        }
    }

    // ---- rowsum: quad-lane reduce + cross-warp(wn) smem atomics ----
    #pragma unroll
    for (int half = 0; half < 2; half++) {
        float v = rs[half];
        v += __shfl_xor_sync(0xffffffffu, v, 1);
        v += __shfl_xor_sync(0xffffffffu, v, 2);
        if (tg == 0)
            atomicAdd(&rowsum[wm * 16 + half * 8 + gid], v);
    }
    __syncthreads();

    // ---- epilogue: out = EV/denom (split bf16), unc += L/denom ----
    #pragma unroll
    for (int half = 0; half < 2; half++) {
        int row = wm * 16 + half * 8 + gid;
        float invd = 1.0f / rowsum[row];
        size_t obase = (size_t)b * SEQ * DMODEL + (size_t)(q0 + row) * DMODEL
                     + h * HD + wn * 16;
        #pragma unroll
        for (int nt = 0; nt < 2; nt++) {
            int col = nt * 8 + tg * 2;
            float v0 = acc_ev[nt][half * 2 + 0] * invd;
            float v1 = acc_ev[nt][half * 2 + 1] * invd;
            __nv_bfloat162 hh, ll;
            split_bf16x2(v0, v1, hh, ll);
            *(__nv_bfloat162*)&outH[obase + col] = hh;
            *(__nv_bfloat162*)&outL[obase + col] = ll;
        }
        if (wn == 0 && tg == 0)
            unc[(size_t)bh * SEQ + q0 + row] += (float)SEQ * invd;
    }
}

// ---------------- finalize --------------------------------------------------
__global__ void finalize_kernel(float* __restrict__ out)
{
    int i = blockIdx.x * blockDim.x + threadIdx.x;
    if (i < BATCH * NHEADS * SEQ) {
        float a = g_unc[i] * 0.25f;
        out[MTOT * DMODEL + i] = a;
        out[MTOT * DMODEL + BATCH * NHEADS * SEQ + i] = (a > 0.3f) ? 1.0f : 0.0f;
    }
}

// ---------------- launch ----------------------------------------------------
extern "C" void kernel_launch(void* const* d_in, const int* in_sizes, int n_in,
                              void* d_out, int out_size)
{
    const float* x      = (const float*)d_in[0];
    const float* Win    = (const float*)d_in[1];
    const float* bin_   = (const float*)d_in[2];
    const float* Wq     = (const float*)d_in[3];
    const float* bq     = (const float*)d_in[4];
    const float* Wk     = (const float*)d_in[5];
    const float* bk     = (const float*)d_in[6];
    const float* Wv     = (const float*)d_in[7];
    const float* bv     = (const float*)d_in[8];
    const float* Wo     = (const float*)d_in[9];
    const float* bo     = (const float*)d_in[10];
    const float* evs    = (const float*)d_in[11];
    const float* evb    = (const float*)d_in[12];
    const float* W1     = (const float*)d_in[13];
    const float* b1     = (const float*)d_in[14];
    const float* W2     = (const float*)d_in[15];
    const float* b2     = (const float*)d_in[16];
    const float* n1g    = (const float*)d_in[17];
    const float* n1b    = (const float*)d_in[18];
    const float* n2g    = (const float*)d_in[19];
    const float* n2b    = (const float*)d_in[20];
    const float* fng    = (const float*)d_in[21];
    const float* fnb    = (const float*)d_in[22];
    const float* Wout   = (const float*)d_in[23];
    const float* bout   = (const float*)d_in[24];
    float* out = (float*)d_out;

    float *ph, *punc, *pbqkv;
    cudaGetSymbolAddress((void**)&ph,    g_h);
    cudaGetSymbolAddress((void**)&punc,  g_unc);
    cudaGetSymbolAddress((void**)&pbqkv, g_bqkv);

    __nv_bfloat16 *xH, *xL, *lnH, *lnL, *qkvH, *qkvL, *attnH, *attnL, *ffH, *ffL;
    cudaGetSymbolAddress((void**)&xH,    g_xH);
    cudaGetSymbolAddress((void**)&xL,    g_xL);
    cudaGetSymbolAddress((void**)&lnH,   g_lnH);
    cudaGetSymbolAddress((void**)&lnL,   g_lnL);
    cudaGetSymbolAddress((void**)&qkvH,  g_qkvH);
    cudaGetSymbolAddress((void**)&qkvL,  g_qkvL);
    cudaGetSymbolAddress((void**)&attnH, g_attnH);
    cudaGetSymbolAddress((void**)&attnL, g_attnL);
    cudaGetSymbolAddress((void**)&ffH,   g_ffH);
    cudaGetSymbolAddress((void**)&ffL,   g_ffL);

    __nv_bfloat16 *WinH, *WinL, *WoutH, *WoutL, *WqkvH, *WqkvL,
                  *WoH, *WoL, *W1H, *W1L, *W2H, *W2L;
    cudaGetSymbolAddress((void**)&WinH,  g_WinH);
    cudaGetSymbolAddress((void**)&WinL,  g_WinL);
    cudaGetSymbolAddress((void**)&WoutH, g_WoutH);
    cudaGetSymbolAddress((void**)&WoutL, g_WoutL);
    cudaGetSymbolAddress((void**)&WqkvH, g_WqkvH);
    cudaGetSymbolAddress((void**)&WqkvL, g_WqkvL);
    cudaGetSymbolAddress((void**)&WoH,   g_WoH);
    cudaGetSymbolAddress((void**)&WoL,   g_WoL);
    cudaGetSymbolAddress((void**)&W1H,   g_W1H);
    cudaGetSymbolAddress((void**)&W1L,   g_W1L);
    cudaGetSymbolAddress((void**)&W2H,   g_W2H);
    cudaGetSymbolAddress((void**)&W2L,   g_W2L);

    cudaFuncSetAttribute(attn_mma, cudaFuncAttributeMaxDynamicSharedMemorySize, ATTN_SMEM);
    cudaFuncSetAttribute(gemm2<0,0>, cudaFuncAttributeMaxDynamicSharedMemorySize, GEMM_SMEM);
    cudaFuncSetAttribute(gemm2<0,1>, cudaFuncAttributeMaxDynamicSharedMemorySize, GEMM_SMEM);
    cudaFuncSetAttribute(gemm2<1,0>, cudaFuncAttributeMaxDynamicSharedMemorySize, GEMM_SMEM);
    cudaFuncSetAttribute(gemm2<2,1>, cudaFuncAttributeMaxDynamicSharedMemorySize, GEMM_SMEM);
    cudaFuncSetAttribute(gemm2_sk,   cudaFuncAttributeMaxDynamicSharedMemorySize, GEMM_SMEM);

    // ---- prep: split weights (transposed) + input x + biases ----
    PrepArgs pa;
    int si = 0, base = 0;
    auto add = [&](const float* src, __nv_bfloat16* hi, __nv_bfloat16* lo, int K, int N) {
        pa.s[si].src = src; pa.s[si].hi = hi; pa.s[si].lo = lo;
        pa.s[si].K = K; pa.s[si].N = N; pa.s[si].base = base;
        base += K * N; si++;
    };
    add(Win,  WinH,  WinL,  DMODEL, DMODEL);
    add(Wout, WoutH, WoutL, DMODEL, DMODEL);
    for (int i = 0; i < NLAYERS; i++) {
        size_t qb = (size_t)i * QKVS * DMODEL;
        add(Wq + (size_t)i * DMODEL * DMODEL, WqkvH + qb,                       WqkvL + qb,                       DMODEL, DMODEL);
        add(Wk + (size_t)i * DMODEL * DMODEL, WqkvH + qb + DMODEL * DMODEL,     WqkvL + qb + DMODEL * DMODEL,     DMODEL, DMODEL);
        add(Wv + (size_t)i * DMODEL * DMODEL, WqkvH + qb + 2 * DMODEL * DMODEL, WqkvL + qb + 2 * DMODEL * DMODEL, DMODEL, DMODEL);
        add(Wo + (size_t)i * DMODEL * DMODEL, WoH + (size_t)i * DMODEL * DMODEL, WoL + (size_t)i * DMODEL * DMODEL, DMODEL, DMODEL);
        add(W1 + (size_t)i * DMODEL * DFF, W1H + (size_t)i * DFF * DMODEL, W1L + (size_t)i * DFF * DMODEL, DMODEL, DFF);
        add(W2 + (size_t)i * DFF * DMODEL, W2H + (size_t)i * DMODEL * DFF, W2L + (size_t)i * DMODEL * DFF, DFF, DMODEL);
    }
    pa.total = base;

    prep_kernel<<<(pa.total + 255) / 256, 256>>>(pa);
    splitx_kernel<<<(MTOT * DMODEL + 255) / 256, 256>>>(x);
    misc_kernel<<<(NLAYERS * QKVS + BATCH * NHEADS * SEQ + 255) / 256, 256>>>(bq, bk, bv);

    const dim3 gD(DMODEL / 64, MTOT / 64);      // (4, 64)  = 256 blocks
    const dim3 gQ(QKVS   / 64, MTOT / 64);      // (12, 64) = 768
    const dim3 gF(DFF    / 64, MTOT / 64);      // (16, 64) = 1024
    const dim3 gW2(DMODEL / 64, MTOT / 64, DFF / KCHUNK);  // (4, 64, 4) = 1024
    const dim3 gA(SEQ / 64, BATCH * NHEADS);    // (32, 16) = 512

    // h = x @ Win + bin
    gemm2<0,0><<<gD, 256, GEMM_SMEM>>>(xH, xL, WinH, WinL, bin_, nullptr,
                                       ph, nullptr, nullptr, DMODEL, DMODEL);

    for (int i = 0; i < NLAYERS; i++) {
        ln_kernel<<<MTOT / 8, 256>>>(ph, n1g + i * DMODEL, n1b + i * DMODEL, lnH, lnL);
        gemm2<0,1><<<gQ, 256, GEMM_SMEM>>>(lnH, lnL,
                                           WqkvH + (size_t)i * QKVS * DMODEL,
                                           WqkvL + (size_t)i * QKVS * DMODEL,
                                           pbqkv + i * QKVS, nullptr,
                                           nullptr, qkvH, qkvL, DMODEL, QKVS);
        attn_mma<<<gA, 256, ATTN_SMEM>>>(qkvH, qkvL, attnH, attnL, punc, evs, evb, i);
        gemm2<1,0><<<gD, 256, GEMM_SMEM>>>(attnH, attnL,
                                           WoH + (size_t)i * DMODEL * DMODEL,
                                           WoL + (size_t)i * DMODEL * DMODEL,
                                           bo + i * DMODEL, ph,
                                           ph, nullptr, nullptr, DMODEL, DMODEL);
        ln_kernel<<<MTOT / 8, 256>>>(ph, n2g + i * DMODEL, n2b + i * DMODEL, lnH, lnL);
        gemm2<2,1><<<gF, 256, GEMM_SMEM>>>(lnH, lnL,
                                           W1H + (size_t)i * DFF * DMODEL,
                                           W1L + (size_t)i * DFF * DMODEL,
                                           b1 + i * DFF, nullptr,
                                           nullptr, ffH, ffL, DMODEL, DFF);
        // h += ff @ W2 + b2  (split-K, atomic accumulate into h)
        gemm2_sk<<<gW2, 256, GEMM_SMEM>>>(ffH, ffL,
                                          W2H + (size_t)i * DMODEL * DFF,
                                          W2L + (size_t)i * DMODEL * DFF,
                                          b2 + i * DMODEL, ph, DFF, DMODEL);
    }

    ln_kernel<<<MTOT / 8, 256>>>(ph, fng, fnb, lnH, lnL);
    gemm2<0,0><<<gD, 256, GEMM_SMEM>>>(lnH, lnL, WoutH, WoutL, bout, nullptr,
                                       out, nullptr, nullptr, DMODEL, DMODEL);

    if (out_size >= MTOT * DMODEL + 2 * BATCH * NHEADS * SEQ)
        finalize_kernel<<<(BATCH * NHEADS * SEQ + 255) / 256, 256>>>(out);
}

// round 11
// speedup vs baseline: 1.1651x; 1.1651x over previous
#include <cuda_runtime.h>
#include <cuda_bf16.h>
#include <math.h>
#include <stdint.h>

// ---------------- problem constants ----------------
#define NLAYERS 4
#define NHEADS  8
#define DMODEL  256
#define DFF     1024
#define BATCH   2
#define SEQ     2048
#define MTOT    (BATCH * SEQ)   // 4096 rows
#define HD      32              // head dim
#define QKVS    768             // fused QKV row stride

// ---------------- scratch (device globals; no allocation allowed) ----------
__device__ float g_h   [MTOT * DMODEL];          // residual stream (fp32)
__device__ float g_unc [BATCH * NHEADS * SEQ];
__device__ float g_bqkv[NLAYERS * QKVS];

// split bf16 activation planes
__device__ __nv_bfloat16 g_xH   [MTOT * DMODEL];
__device__ __nv_bfloat16 g_xL   [MTOT * DMODEL];
__device__ __nv_bfloat16 g_lnH  [MTOT * DMODEL];
__device__ __nv_bfloat16 g_lnL  [MTOT * DMODEL];
__device__ __nv_bfloat16 g_qkvH [MTOT * QKVS];
__device__ __nv_bfloat16 g_qkvL [MTOT * QKVS];
__device__ __nv_bfloat16 g_attnH[MTOT * DMODEL];
__device__ __nv_bfloat16 g_attnL[MTOT * DMODEL];
__device__ __nv_bfloat16 g_ffH  [MTOT * DFF];
__device__ __nv_bfloat16 g_ffL  [MTOT * DFF];

// bf16 split weights (hi/lo planes), transposed to [N][K]
__device__ __nv_bfloat16 g_WinH [DMODEL * DMODEL];
__device__ __nv_bfloat16 g_WinL [DMODEL * DMODEL];
__device__ __nv_bfloat16 g_WoutH[DMODEL * DMODEL];
__device__ __nv_bfloat16 g_WoutL[DMODEL * DMODEL];
__device__ __nv_bfloat16 g_WqkvH[NLAYERS * QKVS * DMODEL];
__device__ __nv_bfloat16 g_WqkvL[NLAYERS * QKVS * DMODEL];
__device__ __nv_bfloat16 g_WoH  [NLAYERS * DMODEL * DMODEL];
__device__ __nv_bfloat16 g_WoL  [NLAYERS * DMODEL * DMODEL];
__device__ __nv_bfloat16 g_W1H  [NLAYERS * DFF * DMODEL];
__device__ __nv_bfloat16 g_W1L  [NLAYERS * DFF * DMODEL];
__device__ __nv_bfloat16 g_W2H  [NLAYERS * DMODEL * DFF];
__device__ __nv_bfloat16 g_W2L  [NLAYERS * DMODEL * DFF];

// ---------------- prep kernels ----------------------------------------------
struct PrepSeg {
    const float* src;
    __nv_bfloat16* hi;
    __nv_bfloat16* lo;
    int K;
    int N;
    int base;      // cumulative element offset
};
struct PrepArgs { PrepSeg s[26]; int total; };

__global__ void prep_kernel(PrepArgs a)
{
    int gidx = blockIdx.x * 256 + threadIdx.x;
    if (gidx >= a.total) return;
    int si = 0;
    #pragma unroll
    for (int i = 1; i < 26; i++)
        if (gidx >= a.s[i].base) si = i;
    PrepSeg sg = a.s[si];
    int idx = gidx - sg.base;
    int k = idx % sg.K, n = idx / sg.K;
    float v = sg.src[(size_t)k * sg.N + n];
    __nv_bfloat16 h = __float2bfloat16(v);
    sg.hi[idx] = h;
    sg.lo[idx] = __float2bfloat16(v - __bfloat162float(h));
}

__global__ void splitx_kernel(const float* __restrict__ x)
{
    int idx = blockIdx.x * 256 + threadIdx.x;
    if (idx < MTOT * DMODEL) {
        float v = x[idx];
        __nv_bfloat16 h = __float2bfloat16(v);
        g_xH[idx] = h;
        g_xL[idx] = __float2bfloat16(v - __bfloat162float(h));
    }
}

__global__ void misc_kernel(const float* __restrict__ bq,
                            const float* __restrict__ bk,
                            const float* __restrict__ bv)
{
    int idx = blockIdx.x * 256 + threadIdx.x;
    if (idx < NLAYERS * QKVS) {
        int l = idx / QKVS, c = idx % QKVS;
        int sec = c >> 8, cc = c & 255;
        const float* s = (sec == 0) ? bq : (sec == 1 ? bk : bv);
        g_bqkv[idx] = s[l * DMODEL + cc];
    }
    int j = idx - NLAYERS * QKVS;
    if (j >= 0 && j < BATCH * NHEADS * SEQ) g_unc[j] = 0.f;
}

// ---------------- layernorm: warp-per-row, no block barriers ---------------
__global__ void __launch_bounds__(256)
ln_kernel(const float* __restrict__ x,
          const float* __restrict__ gamma,
          const float* __restrict__ beta,
          __nv_bfloat16* __restrict__ yH,
          __nv_bfloat16* __restrict__ yL)
{
    int warp = threadIdx.x >> 5, lane = threadIdx.x & 31;
    int row = blockIdx.x * 8 + warp;
    const float* xr = x + (size_t)row * DMODEL + lane * 8;

    float4 a = *(const float4*)xr;
    float4 b = *(const float4*)(xr + 4);

    float s = a.x + a.y + a.z + a.w + b.x + b.y + b.z + b.w;
    #pragma unroll
    for (int o = 16; o > 0; o >>= 1) s += __shfl_xor_sync(0xffffffffu, s, o);
    float mean = s * (1.0f / DMODEL);

    float v[8] = { a.x - mean, a.y - mean, a.z - mean, a.w - mean,
                   b.x - mean, b.y - mean, b.z - mean, b.w - mean };
    float s2 = 0.f;
    #pragma unroll
    for (int i = 0; i < 8; i++) s2 += v[i] * v[i];
    #pragma unroll
    for (int o = 16; o > 0; o >>= 1) s2 += __shfl_xor_sync(0xffffffffu, s2, o);
    float rstd = rsqrtf(s2 * (1.0f / DMODEL) + 1e-5f);

    float4 g0 = *(const float4*)&gamma[lane * 8];
    float4 g1 = *(const float4*)&gamma[lane * 8 + 4];
    float4 be0 = *(const float4*)&beta[lane * 8];
    float4 be1 = *(const float4*)&beta[lane * 8 + 4];
    float gg[8] = { g0.x, g0.y, g0.z, g0.w, g1.x, g1.y, g1.z, g1.w };
    float bb[8] = { be0.x, be0.y, be0.z, be0.w, be1.x, be1.y, be1.z, be1.w };

    __nv_bfloat16 hh[8], ll[8];
    #pragma unroll
    for (int i = 0; i < 8; i++) {
        float y = v[i] * rstd * gg[i] + bb[i];
        __nv_bfloat16 h = __float2bfloat16(y);
        hh[i] = h;
        ll[i] = __float2bfloat16(y - __bfloat162float(h));
    }
    size_t o = (size_t)row * DMODEL + lane * 8;
    *(uint4*)&yH[o] = *(uint4*)hh;
    *(uint4*)&yL[o] = *(uint4*)ll;
}

// ---------------- mma / cp.async helpers ------------------------------------
__device__ __forceinline__ uint32_t smem_u32(const void* p)
{
    return (uint32_t)__cvta_generic_to_shared(p);
}

__device__ __forceinline__ void ldsm_x4(uint32_t& r0, uint32_t& r1,
                                        uint32_t& r2, uint32_t& r3, uint32_t addr)
{
    asm volatile("ldmatrix.sync.aligned.m8n8.x4.shared.b16 {%0,%1,%2,%3}, [%4];\n"
                 : "=r"(r0), "=r"(r1), "=r"(r2), "=r"(r3) : "r"(addr));
}

__device__ __forceinline__ void mma_bf16(float* d, const uint32_t* a, const uint32_t* b)
{
    asm volatile(
        "mma.sync.aligned.m16n8k16.row.col.f32.bf16.bf16.f32 "
        "{%0,%1,%2,%3}, {%4,%5,%6,%7}, {%8,%9}, {%0,%1,%2,%3};\n"
        : "+f"(d[0]), "+f"(d[1]), "+f"(d[2]), "+f"(d[3])
        : "r"(a[0]), "r"(a[1]), "r"(a[2]), "r"(a[3]), "r"(b[0]), "r"(b[1]));
}

__device__ __forceinline__ void split_bf16x2(float a, float b,
                                             __nv_bfloat162& hi, __nv_bfloat162& lo)
{
    __nv_bfloat16 h0 = __float2bfloat16(a);
    __nv_bfloat16 h1 = __float2bfloat16(b);
    hi.x = h0; hi.y = h1;
    lo.x = __float2bfloat16(a - __bfloat162float(h0));
    lo.y = __float2bfloat16(b - __bfloat162float(h1));
}

__device__ __forceinline__ void cp16(void* dst, const void* src)
{
    asm volatile("cp.async.cg.shared.global [%0], [%1], 16;\n"
                 :: "r"(smem_u32(dst)), "l"(src));
}
__device__ __forceinline__ void cp_commit()
{
    asm volatile("cp.async.commit_group;\n");
}
template <int N>
__device__ __forceinline__ void cp_wait()
{
    asm volatile("cp.async.wait_group %0;\n" :: "n"(N));
}

// ---------------- pipelined pre-split bf16 GEMM -----------------------------
// Tile 64x64, BK=64 per stage (halved barrier count, doubled prefetch
// distance vs BK=32), 256 threads (8 warps, 2x4 grid, 32x16 per warp),
// 2-stage cp.async, one __syncthreads per 64-K iter.
#define GROW 72                               // smem row stride (elems)
#define GASZ (64 * GROW)                      // one plane (4608 elems)
#define GSTG (4 * GASZ)                       // Ah|Al|Bh|Bl per stage (18432)
#define GEMM_SMEM (2 * GSTG * 2)              // bytes = 73728

template <int EPI, int SPLIT>
__global__ void __launch_bounds__(256)
gemm2(const __nv_bfloat16* __restrict__ Ah_, const __nv_bfloat16* __restrict__ Al_,
      const __nv_bfloat16* __restrict__ Bh_, const __nv_bfloat16* __restrict__ Bl_,
      const float* __restrict__ bias, const float* __restrict__ res,
      float* __restrict__ C, __nv_bfloat16* __restrict__ Ch, __nv_bfloat16* __restrict__ Cl,
      int K, int ldc)
{
    extern __shared__ __align__(16) __nv_bfloat16 sm[];

    int tid = threadIdx.x, lane = tid & 31, warp = tid >> 5;
    int m0 = blockIdx.y * 64, n0 = blockIdx.x * 64;
    int wm = warp >> 2, wn = warp & 3;        // 2x4 warp grid, 32x16 per warp

    int gq = lane >> 3, lr = lane & 7;
    int frow  = (gq & 1) * 8 + lr;
    int fcolh = (gq >> 1) * 8;

    float acc[2][2][4] = {};

    // per-thread load: 64 rows x 8 chunks(16B) = 512 chunks per plane;
    // 256 threads -> 2 chunks/thread/plane (8 cp16 per stage).
    int r0_ = tid >> 3, c0_ = (tid & 7) * 8;
    int r1_ = (tid + 256) >> 3;

    auto load_stage = [&](int stage, int k0) {
        __nv_bfloat16* base = sm + stage * GSTG;
        cp16(&base[r0_ * GROW + c0_],                  &Ah_[(size_t)(m0 + r0_) * K + k0 + c0_]);
        cp16(&base[r1_ * GROW + c0_],                  &Ah_[(size_t)(m0 + r1_) * K + k0 + c0_]);
        cp16(&base[GASZ + r0_ * GROW + c0_],           &Al_[(size_t)(m0 + r0_) * K + k0 + c0_]);
        cp16(&base[GASZ + r1_ * GROW + c0_],           &Al_[(size_t)(m0 + r1_) * K + k0 + c0_]);
        cp16(&base[2 * GASZ + r0_ * GROW + c0_],       &Bh_[(size_t)(n0 + r0_) * K + k0 + c0_]);
        cp16(&base[2 * GASZ + r1_ * GROW + c0_],       &Bh_[(size_t)(n0 + r1_) * K + k0 + c0_]);
        cp16(&base[3 * GASZ + r0_ * GROW + c0_],       &Bl_[(size_t)(n0 + r0_) * K + k0 + c0_]);
        cp16(&base[3 * GASZ + r1_ * GROW + c0_],       &Bl_[(size_t)(n0 + r1_) * K + k0 + c0_]);
        cp_commit();
    };

    load_stage(0, 0);

    int kiters = K >> 6;
    for (int it = 0; it < kiters; it++) {
        int stage = it & 1;
        cp_wait<0>();
        __syncthreads();                       // stage ready + prev compute done
        if (it + 1 < kiters) load_stage(stage ^ 1, (it + 1) * 64);

        __nv_bfloat16* sAh = sm + stage * GSTG;
        __nv_bfloat16* sAl = sAh + GASZ;
        __nv_bfloat16* sBh = sAh + 2 * GASZ;
        __nv_bfloat16* sBl = sAh + 3 * GASZ;

        #pragma unroll
        for (int s = 0; s < 4; s++) {
            int kb = s * 16;
            uint32_t ah[2][4], al[2][4], bh[2][2], bl[2][2];
            #pragma unroll
            for (int mt = 0; mt < 2; mt++) {
                uint32_t addr = smem_u32(&sAh[(wm * 32 + mt * 16 + frow) * GROW + kb + fcolh]);
                ldsm_x4(ah[mt][0], ah[mt][1], ah[mt][2], ah[mt][3], addr);
                addr = smem_u32(&sAl[(wm * 32 + mt * 16 + frow) * GROW + kb + fcolh]);
                ldsm_x4(al[mt][0], al[mt][1], al[mt][2], al[mt][3], addr);
            }
            {
                uint32_t r0, r1, r2, r3;
                uint32_t addr = smem_u32(&sBh[(wn * 16 + frow) * GROW + kb + fcolh]);
                ldsm_x4(r0, r1, r2, r3, addr);
                bh[0][0] = r0; bh[1][0] = r1; bh[0][1] = r2; bh[1][1] = r3;
                addr = smem_u32(&sBl[(wn * 16 + frow) * GROW + kb + fcolh]);
                ldsm_x4(r0, r1, r2, r3, addr);
                bl[0][0] = r0; bl[1][0] = r1; bl[0][1] = r2; bl[1][1] = r3;
            }
            #pragma unroll
            for (int mt = 0; mt < 2; mt++)
                #pragma unroll
                for (int nt = 0; nt < 2; nt++) {
                    mma_bf16(acc[mt][nt], ah[mt], bh[nt]);
                    mma_bf16(acc[mt][nt], ah[mt], bl[nt]);
                    mma_bf16(acc[mt][nt], al[mt], bh[nt]);
                }
        }
    }

    // ---- epilogue: warp owns 32 rows x 16 cols ----
    int gid = lane >> 2, tg = lane & 3;
    #pragma unroll
    for (int mt = 0; mt < 2; mt++) {
        int row0 = m0 + wm * 32 + mt * 16 + gid;
        #pragma unroll
        for (int nt = 0; nt < 2; nt++) {
            int col = n0 + wn * 16 + nt * 8 + tg * 2;
            #pragma unroll
            for (int half = 0; half < 2; half++) {
                int row = row0 + half * 8;
                float v0 = acc[mt][nt][half * 2 + 0] + bias[col];
                float v1 = acc[mt][nt][half * 2 + 1] + bias[col + 1];
                if (EPI == 1) {
                    v0 += res[(size_t)row * ldc + col];
                    v1 += res[(size_t)row * ldc + col + 1];
                }
                if (EPI == 2) {
                    v0 = 0.5f * v0 * (1.0f + erff(v0 * 0.70710678118654752f));
                    v1 = 0.5f * v1 * (1.0f + erff(v1 * 0.70710678118654752f));
                }
                if (SPLIT) {
                    __nv_bfloat162 hh, ll;
                    split_bf16x2(v0, v1, hh, ll);
                    *(__nv_bfloat162*)&Ch[(size_t)row * ldc + col] = hh;
                    *(__nv_bfloat162*)&Cl[(size_t)row * ldc + col] = ll;
                } else {
                    float2 f2; f2.x = v0; f2.y = v1;
                    *(float2*)&C[(size_t)row * ldc + col] = f2;
                }
            }
        }
    }
}

// ---------------- tensor-core fused evidential attention (128-q tiles) -----
#define ATTN_SMEM 77312

__global__ void __launch_bounds__(256)
attn_mma(const __nv_bfloat16* __restrict__ qkvH,
         const __nv_bfloat16* __restrict__ qkvL,
         __nv_bfloat16* __restrict__ outH,
         __nv_bfloat16* __restrict__ outL,
         float* __restrict__ unc,
         const float* __restrict__ ev_scale,
         const float* __restrict__ ev_bias,
         int layer)
{
    extern __shared__ __align__(16) char smraw[];
    __nv_bfloat16* sQh = (__nv_bfloat16*)smraw;          // [128][40]
    __nv_bfloat16* sQl = sQh + 128 * 40;
    __nv_bfloat16* sKh = sQl + 128 * 40;                 // [64][40]
    __nv_bfloat16* sKl = sKh + 64 * 40;
    __nv_bfloat16* sVh = sKl + 64 * 40;                  // [32][72] transposed
    __nv_bfloat16* sVl = sVh + 32 * 72;
    __nv_bfloat16* sEh = sVl + 32 * 72;                  // [128][72]
    __nv_bfloat16* sEl = sEh + 128 * 72;
    float* rowsum = (float*)(sEl + 128 * 72);            // [128]

    int tid = threadIdx.x, lane = tid & 31, warp = tid >> 5;
    int bh = blockIdx.y;
    int b = bh >> 3, h = bh & 7;
    int q0 = blockIdx.x * 128;

    float scale = ev_scale[layer];
    float opb   = 1.0f + ev_bias[layer];
    const float inv_sqrt_hd = 0.17677669529663687f;

    const __nv_bfloat16* QbH = qkvH + (size_t)b * SEQ * QKVS + h * HD;
    const __nv_bfloat16* QbL = qkvL + (size_t)b * SEQ * QKVS + h * HD;
    const __nv_bfloat16* KbH = QbH + DMODEL;
    const __nv_bfloat16* KbL = QbL + DMODEL;
    const __nv_bfloat16* VbH = QbH + 2 * DMODEL;
    const __nv_bfloat16* VbL = QbL + 2 * DMODEL;

    if (tid < 128) rowsum[tid] = 0.f;

    #pragma unroll
    for (int e = 0; e < 2; e++) {
        int f = tid + e * 256;
        int m = f >> 2, c8 = (f & 3) * 8;
        *(uint4*)&sQh[m * 40 + c8] = *(const uint4*)&QbH[(size_t)(q0 + m) * QKVS + c8];
        *(uint4*)&sQl[m * 40 + c8] = *(const uint4*)&QbL[(size_t)(q0 + m) * QKVS + c8];
    }

    int wm = warp >> 1, wn = warp & 1;
    int gq = lane >> 3, lr = lane & 7;
    int frow = (gq & 1) * 8 + lr, fcolh = (gq >> 1) * 8;
    int gid = lane >> 2, tg = lane & 3;

    float acc_ev[4][4] = {};
    float rs[2][2] = {};

    for (int kb0 = 0; kb0 < SEQ; kb0 += 64) {
        __syncthreads();
        {
            int m = tid >> 2, c8 = (tid & 3) * 8;
            *(uint4*)&sKh[m * 40 + c8] = *(const uint4*)&KbH[(size_t)(kb0 + m) * QKVS + c8];
            *(uint4*)&sKl[m * 40 + c8] = *(const uint4*)&KbL[(size_t)(kb0 + m) * QKVS + c8];
        }
        #pragma unroll
        for (int e = 0; e < 4; e++) {
            int f = tid + e * 256;
            int key = f >> 4, dp = (f & 15) * 2;
            __nv_bfloat162 vh = *(const __nv_bfloat162*)&VbH[(size_t)(kb0 + key) * QKVS + dp];
            __nv_bfloat162 vl = *(const __nv_bfloat162*)&VbL[(size_t)(kb0 + key) * QKVS + dp];
            sVh[dp * 72 + key]       = vh.x;
            sVh[(dp + 1) * 72 + key] = vh.y;
            sVl[dp * 72 + key]       = vl.x;
            sVl[(dp + 1) * 72 + key] = vl.y;
        }
        __syncthreads();

        float acc_s[2][4][4] = {};
        #pragma unroll
        for (int s = 0; s < 2; s++) {
            int kb = s * 16;
            uint32_t ah[2][4], al[2][4], bhf[4][2], blf[4][2];
            #pragma unroll
            for (int mt = 0; mt < 2; mt++) {
                uint32_t addr = smem_u32(&sQh[(wm * 32 + mt * 16 + frow) * 40 + kb + fcolh]);
                ldsm_x4(ah[mt][0], ah[mt][1], ah[mt][2], ah[mt][3], addr);
                addr = smem_u32(&sQl[(wm * 32 + mt * 16 + frow) * 40 + kb + fcolh]);
                ldsm_x4(al[mt][0], al[mt][1], al[mt][2], al[mt][3], addr);
            }
            #pragma unroll
            for (int np = 0; np < 2; np++) {
                uint32_t r0, r1, r2, r3;
                uint32_t addr = smem_u32(&sKh[(wn * 32 + np * 16 + frow) * 40 + kb + fcolh]);
                ldsm_x4(r0, r1, r2, r3, addr);
                bhf[np * 2][0] = r0; bhf[np * 2 + 1][0] = r1;
                bhf[np * 2][1] = r2; bhf[np * 2 + 1][1] = r3;
                addr = smem_u32(&sKl[(wn * 32 + np * 16 + frow) * 40 + kb + fcolh]);
                ldsm_x4(r0, r1, r2, r3, addr);
                blf[np * 2][0] = r0; blf[np * 2 + 1][0] = r1;
                blf[np * 2][1] = r2; blf[np * 2 + 1][1] = r3;
            }
            #pragma unroll
            for (int mt = 0; mt < 2; mt++)
                #pragma unroll
                for (int nt = 0; nt < 4; nt++) {
                    mma_bf16(acc_s[mt][nt], ah[mt], bhf[nt]);
                    mma_bf16(acc_s[mt][nt], ah[mt], blf[nt]);
                    mma_bf16(acc_s[mt][nt], al[mt], bhf[nt]);
                }
        }

        #pragma unroll
        for (int mt = 0; mt < 2; mt++) {
            #pragma unroll
            for (int half = 0; half < 2; half++) {
                int row = wm * 32 + mt * 16 + half * 8 + gid;
                #pragma unroll
                for (int nt = 0; nt < 4; nt++) {
                    float e0 = fmaf(scale, __expf(acc_s[mt][nt][half * 2 + 0] * inv_sqrt_hd), opb);
                    float e1 = fmaf(scale, __expf(acc_s[mt][nt][half * 2 + 1] * inv_sqrt_hd), opb);
                    rs[mt][half] += e0 + e1;
                    int col = wn * 32 + nt * 8 + tg * 2;
                    __nv_bfloat162 hh, ll;
                    split_bf16x2(e0, e1, hh, ll);
                    *(__nv_bfloat162*)&sEh[row * 72 + col] = hh;
                    *(__nv_bfloat162*)&sEl[row * 72 + col] = ll;
                }
            }
        }
        __syncthreads();

        #pragma unroll
        for (int kb = 0; kb < 64; kb += 16) {
            uint32_t eh[4], el[4], vh[4][2], vl[4][2];
            uint32_t addr = smem_u32(&sEh[(warp * 16 + frow) * 72 + kb + fcolh]);
            ldsm_x4(eh[0], eh[1], eh[2], eh[3], addr);
            addr = smem_u32(&sEl[(warp * 16 + frow) * 72 + kb + fcolh]);
            ldsm_x4(el[0], el[1], el[2], el[3], addr);
            #pragma unroll
            for (int np = 0; np < 2; np++) {
                uint32_t r0, r1, r2, r3;
                addr = smem_u32(&sVh[(np * 16 + frow) * 72 + kb + fcolh]);
                ldsm_x4(r0, r1, r2, r3, addr);
                vh[np * 2][0] = r0; vh[np * 2 + 1][0] = r1;
                vh[np * 2][1] = r2; vh[np * 2 + 1][1] = r3;
                addr = smem_u32(&sVl[(np * 16 + frow) * 72 + kb + fcolh]);
                ldsm_x4(r0, r1, r2, r3, addr);
                vl[np * 2][0] = r0; vl[np * 2 + 1][0] = r1;
                vl[np * 2][1] = r2; vl[np * 2 + 1][1] = r3;
            }
            #pragma unroll
            for (int nt = 0; nt < 4; nt++) {
                mma_bf16(acc_ev[nt], eh, vh[nt]);
                mma_bf16(acc_ev[nt], eh, vl[nt]);
                mma_bf16(acc_ev[nt], el, vh[nt]);
            }
        }
    }

    #pragma unroll
    for (int mt = 0; mt < 2; mt++)
        #pragma unroll
        for (int half = 0; half < 2; half++) {
            float v = rs[mt][half];
            v += __shfl_xor_sync(0xffffffffu, v, 1);
            v += __shfl_xor_sync(0xffffffffu, v, 2);
            if (tg == 0)
                atomicAdd(&rowsum[wm * 32 + mt * 16 + half * 8 + gid], v);
        }
    __syncthreads();

    #pragma unroll
    for (int half = 0; half < 2; half++) {
        int row = warp * 16 + half * 8 + gid;
        float invd = 1.0f / rowsum[row];
        size_t obase = (size_t)b * SEQ * DMODEL + (size_t)(q0 + row) * DMODEL + h * HD;
        #pragma unroll
        for (int nt = 0; nt < 4; nt++) {
            int col = nt * 8 + tg * 2;
            float v0 = acc_ev[nt][half * 2 + 0] * invd;
            float v1 = acc_ev[nt][half * 2 + 1] * invd;
            __nv_bfloat162 hh, ll;
            split_bf16x2(v0, v1, hh, ll);
            *(__nv_bfloat162*)&outH[obase + col] = hh;
            *(__nv_bfloat162*)&outL[obase + col] = ll;
        }
        if (tg == 0)
            unc[(size_t)bh * SEQ + q0 + row] += (float)SEQ * invd;
    }
}

// ---------------- finalize --------------------------------------------------
__global__ void finalize_kernel(float* __restrict__ out)
{
    int i = blockIdx.x * blockDim.x + threadIdx.x;
    if (i < BATCH * NHEADS * SEQ) {
        float a = g_unc[i] * 0.25f;
        out[MTOT * DMODEL + i] = a;
        out[MTOT * DMODEL + BATCH * NHEADS * SEQ + i] = (a > 0.3f) ? 1.0f : 0.0f;
    }
}

// ---------------- launch ----------------------------------------------------
extern "C" void kernel_launch(void* const* d_in, const int* in_sizes, int n_in,
                              void* d_out, int out_size)
{
    const float* x      = (const float*)d_in[0];
    const float* Win    = (const float*)d_in[1];
    const float* bin_   = (const float*)d_in[2];
    const float* Wq     = (const float*)d_in[3];
    const float* bq     = (const float*)d_in[4];
    const float* Wk     = (const float*)d_in[5];
    const float* bk     = (const float*)d_in[6];
    const float* Wv     = (const float*)d_in[7];
    const float* bv     = (const float*)d_in[8];
    const float* Wo     = (const float*)d_in[9];
    const float* bo     = (const float*)d_in[10];
    const float* evs    = (const float*)d_in[11];
    const float* evb    = (const float*)d_in[12];
    const float* W1     = (const float*)d_in[13];
    const float* b1     = (const float*)d_in[14];
    const float* W2     = (const float*)d_in[15];
    const float* b2     = (const float*)d_in[16];
    const float* n1g    = (const float*)d_in[17];
    const float* n1b    = (const float*)d_in[18];
    const float* n2g    = (const float*)d_in[19];
    const float* n2b    = (const float*)d_in[20];
    const float* fng    = (const float*)d_in[21];
    const float* fnb    = (const float*)d_in[22];
    const float* Wout   = (const float*)d_in[23];
    const float* bout   = (const float*)d_in[24];
    float* out = (float*)d_out;

    float *ph, *punc, *pbqkv;
    cudaGetSymbolAddress((void**)&ph,    g_h);
    cudaGetSymbolAddress((void**)&punc,  g_unc);
    cudaGetSymbolAddress((void**)&pbqkv, g_bqkv);

    __nv_bfloat16 *xH, *xL, *lnH, *lnL, *qkvH, *qkvL, *attnH, *attnL, *ffH, *ffL;
    cudaGetSymbolAddress((void**)&xH,    g_xH);
    cudaGetSymbolAddress((void**)&xL,    g_xL);
    cudaGetSymbolAddress((void**)&lnH,   g_lnH);
    cudaGetSymbolAddress((void**)&lnL,   g_lnL);
    cudaGetSymbolAddress((void**)&qkvH,  g_qkvH);
    cudaGetSymbolAddress((void**)&qkvL,  g_qkvL);
    cudaGetSymbolAddress((void**)&attnH, g_attnH);
    cudaGetSymbolAddress((void**)&attnL, g_attnL);
    cudaGetSymbolAddress((void**)&ffH,   g_ffH);
    cudaGetSymbolAddress((void**)&ffL,   g_ffL);

    __nv_bfloat16 *WinH, *WinL, *WoutH, *WoutL, *WqkvH, *WqkvL,
                  *WoH, *WoL, *W1H, *W1L, *W2H, *W2L;
    cudaGetSymbolAddress((void**)&WinH,  g_WinH);
    cudaGetSymbolAddress((void**)&WinL,  g_WinL);
    cudaGetSymbolAddress((void**)&WoutH, g_WoutH);
    cudaGetSymbolAddress((void**)&WoutL, g_WoutL);
    cudaGetSymbolAddress((void**)&WqkvH, g_WqkvH);
    cudaGetSymbolAddress((void**)&WqkvL, g_WqkvL);
    cudaGetSymbolAddress((void**)&WoH,   g_WoH);
    cudaGetSymbolAddress((void**)&WoL,   g_WoL);
    cudaGetSymbolAddress((void**)&W1H,   g_W1H);
    cudaGetSymbolAddress((void**)&W1L,   g_W1L);
    cudaGetSymbolAddress((void**)&W2H,   g_W2H);
    cudaGetSymbolAddress((void**)&W2L,   g_W2L);

    cudaFuncSetAttribute(attn_mma, cudaFuncAttributeMaxDynamicSharedMemorySize, ATTN_SMEM);
    cudaFuncSetAttribute(gemm2<0,0>, cudaFuncAttributeMaxDynamicSharedMemorySize, GEMM_SMEM);
    cudaFuncSetAttribute(gemm2<0,1>, cudaFuncAttributeMaxDynamicSharedMemorySize, GEMM_SMEM);
    cudaFuncSetAttribute(gemm2<1,0>, cudaFuncAttributeMaxDynamicSharedMemorySize, GEMM_SMEM);
    cudaFuncSetAttribute(gemm2<2,1>, cudaFuncAttributeMaxDynamicSharedMemorySize, GEMM_SMEM);

    // ---- prep: split weights (transposed) + input x + biases ----
    PrepArgs pa;
    int si = 0, base = 0;
    auto add = [&](const float* src, __nv_bfloat16* hi, __nv_bfloat16* lo, int K, int N) {
        pa.s[si].src = src; pa.s[si].hi = hi; pa.s[si].lo = lo;
        pa.s[si].K = K; pa.s[si].N = N; pa.s[si].base = base;
        base += K * N; si++;
    };
    add(Win,  WinH,  WinL,  DMODEL, DMODEL);
    add(Wout, WoutH, WoutL, DMODEL, DMODEL);
    for (int i = 0; i < NLAYERS; i++) {
        size_t qb = (size_t)i * QKVS * DMODEL;
        add(Wq + (size_t)i * DMODEL * DMODEL, WqkvH + qb,                       WqkvL + qb,                       DMODEL, DMODEL);
        add(Wk + (size_t)i * DMODEL * DMODEL, WqkvH + qb + DMODEL * DMODEL,     WqkvL + qb + DMODEL * DMODEL,     DMODEL, DMODEL);
        add(Wv + (size_t)i * DMODEL * DMODEL, WqkvH + qb + 2 * DMODEL * DMODEL, WqkvL + qb + 2 * DMODEL * DMODEL, DMODEL, DMODEL);
        add(Wo + (size_t)i * DMODEL * DMODEL, WoH + (size_t)i * DMODEL * DMODEL, WoL + (size_t)i * DMODEL * DMODEL, DMODEL, DMODEL);
        add(W1 + (size_t)i * DMODEL * DFF, W1H + (size_t)i * DFF * DMODEL, W1L + (size_t)i * DFF * DMODEL, DMODEL, DFF);
        add(W2 + (size_t)i * DFF * DMODEL, W2H + (size_t)i * DMODEL * DFF, W2L + (size_t)i * DMODEL * DFF, DFF, DMODEL);
    }
    pa.total = base;

    prep_kernel<<<(pa.total + 255) / 256, 256>>>(pa);
    splitx_kernel<<<(MTOT * DMODEL + 255) / 256, 256>>>(x);
    misc_kernel<<<(NLAYERS * QKVS + BATCH * NHEADS * SEQ + 255) / 256, 256>>>(bq, bk, bv);

    const dim3 gD(DMODEL / 64, MTOT / 64);      // (4, 64)  = 256 blocks
    const dim3 gQ(QKVS   / 64, MTOT / 64);      // (12, 64) = 768
    const dim3 gF(DFF    / 64, MTOT / 64);      // (16, 64) = 1024
    const dim3 gA(SEQ / 128, BATCH * NHEADS);   // (16, 16) = 256

    // h = x @ Win + bin
    gemm2<0,0><<<gD, 256, GEMM_SMEM>>>(xH, xL, WinH, WinL, bin_, nullptr,
                                       ph, nullptr, nullptr, DMODEL, DMODEL);

    for (int i = 0; i < NLAYERS; i++) {
        ln_kernel<<<MTOT / 8, 256>>>(ph, n1g + i * DMODEL, n1b + i * DMODEL, lnH, lnL);
        gemm2<0,1><<<gQ, 256, GEMM_SMEM>>>(lnH, lnL,
                                           WqkvH + (size_t)i * QKVS * DMODEL,
                                           WqkvL + (size_t)i * QKVS * DMODEL,
                                           pbqkv + i * QKVS, nullptr,
                                           nullptr, qkvH, qkvL, DMODEL, QKVS);
        attn_mma<<<gA, 256, ATTN_SMEM>>>(qkvH, qkvL, attnH, attnL, punc, evs, evb, i);
        gemm2<1,0><<<gD, 256, GEMM_SMEM>>>(attnH, attnL,
                                           WoH + (size_t)i * DMODEL * DMODEL,
                                           WoL + (size_t)i * DMODEL * DMODEL,
                                           bo + i * DMODEL, ph,
                                           ph, nullptr, nullptr, DMODEL, DMODEL);
        ln_kernel<<<MTOT / 8, 256>>>(ph, n2g + i * DMODEL, n2b + i * DMODEL, lnH, lnL);
        gemm2<2,1><<<gF, 256, GEMM_SMEM>>>(lnH, lnL,
                                           W1H + (size_t)i * DFF * DMODEL,
                                           W1L + (size_t)i * DFF * DMODEL,
                                           b1 + i * DFF, nullptr,
                                           nullptr, ffH, ffL, DMODEL, DFF);
        gemm2<1,0><<<gD, 256, GEMM_SMEM>>>(ffH, ffL,
                                           W2H + (size_t)i * DMODEL * DFF,
                                           W2L + (size_t)i * DMODEL * DFF,
                                           b2 + i * DMODEL, ph,
                                           ph, nullptr, nullptr, DFF, DMODEL);
    }

    ln_kernel<<<MTOT / 8, 256>>>(ph, fng, fnb, lnH, lnL);
    gemm2<0,0><<<gD, 256, GEMM_SMEM>>>(lnH, lnL, WoutH, WoutL, bout, nullptr,
                                       out, nullptr, nullptr, DMODEL, DMODEL);

    if (out_size >= MTOT * DMODEL + 2 * BATCH * NHEADS * SEQ)
        finalize_kernel<<<(BATCH * NHEADS * SEQ + 255) / 256, 256>>>(out);
}